// round 11
// baseline (speedup 1.0000x reference)
#include <cuda_runtime.h>
#include <cuda_bf16.h>
#include <mma.h>
#include <math.h>

using namespace nvcuda;

// ---------------------------------------------------------------------------
// Problem constants
// ---------------------------------------------------------------------------
#define TT      4096
#define NHEADS  16
#define BB      4
#define BH      64
#define DPH     64
#define HID     1024
#define NHASH   2
#define NBUCK   64
#define WW      64
#define CCHUNK  128
#define MTOT    16384

typedef unsigned long long u64;

// ---- packed fp32x2 helpers ------------------------------------------------
__device__ __forceinline__ void fma2(u64& d, u64 a, u64 b) {
    asm("fma.rn.f32x2 %0, %1, %2, %0;" : "+l"(d) : "l"(a), "l"(b));
}
__device__ __forceinline__ u64 fma2o(u64 a, u64 b, u64 c) {
    u64 d; asm("fma.rn.f32x2 %0, %1, %2, %3;" : "=l"(d) : "l"(a), "l"(b), "l"(c));
    return d;
}
__device__ __forceinline__ u64 bcast2(float f) {
    u64 r; unsigned int u = __float_as_uint(f);
    asm("mov.b64 %0, {%1, %1};" : "=l"(r) : "r"(u));
    return r;
}
__device__ __forceinline__ float2 unpack2(u64 v) {
    unsigned int lo, hi;
    asm("mov.b64 {%0, %1}, %2;" : "=r"(lo), "=r"(hi) : "l"(v));
    return make_float2(__uint_as_float(lo), __uint_as_float(hi));
}

// ---------------------------------------------------------------------------
// Device scratch (static).
// g_qk: qk result, later reused as combine output [b,t,n,d].
// g_ab0/g_ab1: bf16 planes of the tensor-GEMM A operand (x, later comb).
// g_wb0/g_wb1: bf16 planes of the tensor-GEMM B operand (wv, later wo).
// ---------------------------------------------------------------------------
__device__ float          g_qk  [(size_t)BH * TT * DPH];
__device__ float          g_v   [(size_t)BH * TT * DPH];
__device__ float          g_o   [(size_t)BH * NHASH * TT * DPH];
__device__ float          g_lse [(size_t)BH * NHASH * TT];
__device__ int            g_st  [(size_t)BH * NHASH * TT];
__device__ unsigned char  g_bkt [(size_t)BH * NHASH * TT];
__device__ __nv_bfloat16  g_ab0 [(size_t)MTOT * HID];   // 32 MB
__device__ __nv_bfloat16  g_ab1 [(size_t)MTOT * HID];   // 32 MB
__device__ __nv_bfloat16  g_wb0 [(size_t)HID * HID];    //  2 MB
__device__ __nv_bfloat16  g_wb1 [(size_t)HID * HID];    //  2 MB

// ---------------------------------------------------------------------------
// fp32 -> 2 bf16 planes (hi + residual). Bit-identical to R10's in-GEMM split.
// ---------------------------------------------------------------------------
__global__ __launch_bounds__(256)
void cvt2_k(const float* __restrict__ src, __nv_bfloat16* __restrict__ p0,
            __nv_bfloat16* __restrict__ p1, int n4)
{
    int i = blockIdx.x * 256 + threadIdx.x;
    if (i >= n4) return;
    float4 v = ((const float4*)src)[i];
    float va[4] = {v.x, v.y, v.z, v.w};
    __nv_bfloat16 t0[4], t1[4];
#pragma unroll
    for (int j = 0; j < 4; j++) {
        t0[j] = __float2bfloat16_rn(va[j]);
        t1[j] = __float2bfloat16_rn(va[j] - __bfloat162float(t0[j]));
    }
    ((uint2*)p0)[i] = *(uint2*)t0;
    ((uint2*)p1)[i] = *(uint2*)t1;
}

// ===========================================================================
// SCALAR fp32 SGEMM (exact; qk only -- feeds LSH argmax decisions).
// ===========================================================================
__global__ __launch_bounds__(256)
void sgemm_qk_k(const float* __restrict__ A, const float* __restrict__ B,
                float* __restrict__ C, int M, int N, int K)
{
    __shared__ __align__(16) float As[8][128];
    __shared__ __align__(16) float Bs[8][128];

    const int tid  = threadIdx.x;
    const int brow = blockIdx.y * 128;
    const int bcol = blockIdx.x * 128;
    const int tr   = (tid >> 4) * 8;
    const int tc   = (tid & 15) * 8;

    const int a_row = tid >> 1;
    const int a_col = (tid & 1) * 4;
    const int b_row = tid >> 5;
    const int b_col = (tid & 31) * 4;

    const float* Ap = A + (size_t)(brow + a_row) * K + a_col;
    const float* Bp = B + (size_t)b_row * N + bcol + b_col;

    float acc[8][8];
#pragma unroll
    for (int y = 0; y < 8; y++)
#pragma unroll
        for (int x = 0; x < 8; x++) acc[y][x] = 0.f;

    float4 av = *(const float4*)Ap;  Ap += 8;
    float4 bv = *(const float4*)Bp;  Bp += (size_t)8 * N;

    for (int k0 = 0; k0 < K; k0 += 8) {
        As[a_col + 0][a_row] = av.x;
        As[a_col + 1][a_row] = av.y;
        As[a_col + 2][a_row] = av.z;
        As[a_col + 3][a_row] = av.w;
        *(float4*)&Bs[b_row][b_col] = bv;
        __syncthreads();

        if (k0 + 8 < K) {
            av = *(const float4*)Ap;  Ap += 8;
            bv = *(const float4*)Bp;  Bp += (size_t)8 * N;
        }

#pragma unroll
        for (int kk = 0; kk < 8; kk++) {
            float4 a0 = *(const float4*)&As[kk][tr];
            float4 a1 = *(const float4*)&As[kk][tr + 4];
            float4 b0 = *(const float4*)&Bs[kk][tc];
            float4 b1 = *(const float4*)&Bs[kk][tc + 4];
            float ar[8] = {a0.x, a0.y, a0.z, a0.w, a1.x, a1.y, a1.z, a1.w};
            float br[8] = {b0.x, b0.y, b0.z, b0.w, b1.x, b1.y, b1.z, b1.w};
#pragma unroll
            for (int y = 0; y < 8; y++)
#pragma unroll
                for (int x = 0; x < 8; x++) acc[y][x] += ar[y] * br[x];
        }
        __syncthreads();
    }

#pragma unroll
    for (int y = 0; y < 8; y++) {
        int m = brow + tr + y;
        int b = m >> 12;
        int t = m & (TT - 1);
        int col0 = bcol + tc;
        int n = col0 >> 6;
        int d = col0 & 63;
        float* cp = C + (((size_t)(b * NHEADS + n) * TT + t) * DPH + d);
        *(float4*)(cp)     = make_float4(acc[y][0], acc[y][1], acc[y][2], acc[y][3]);
        *(float4*)(cp + 4) = make_float4(acc[y][4], acc[y][5], acc[y][6], acc[y][7]);
    }
}

// ===========================================================================
// bf16 tensor GEMM on pre-split planes: D = A0B0 + A0B1 + A1B0.
// No conversion math in the hot loop; KSTEP=32; 128x128 tile, 8 warps.
// mode 0: C row-major [M,N];  mode 1: per-head remap (ld=64 in-tile).
// ===========================================================================
#define KSTEP 32
#define LDA   48    // 32 + 16 pad elems (96B rows; 16B multiple)
#define LDB   136   // 128 + 8 pad elems (272B rows; 16B multiple)

static_assert((2 * 128 * LDA + 2 * KSTEP * LDB) * 2 <= 48 * 1024, "smem");

__global__ __launch_bounds__(256)
void tgemm_k(const __nv_bfloat16* __restrict__ A0, const __nv_bfloat16* __restrict__ A1,
             const __nv_bfloat16* __restrict__ B0, const __nv_bfloat16* __restrict__ B1,
             float* __restrict__ C, int M, int N, int K, int mode)
{
    __shared__ __align__(32) __nv_bfloat16 As[2][128][LDA];
    __shared__ __align__(32) __nv_bfloat16 Bs[2][KSTEP][LDB];

    const int tid  = threadIdx.x;
    const int wid  = tid >> 5;
    const int brow = blockIdx.y * 128;
    const int bcol = blockIdx.x * 128;
    const int wm   = (wid >> 2) * 64;
    const int wn   = (wid & 3) * 32;

    // A tile 128x32 per plane: 512 8-elem chunks; 2 chunks/thread/plane
    // chunk c: row = c>>2 (0..127), col = (c&3)*8
    const int ac0 = tid, ac1 = tid + 256;
    const int ar0 = ac0 >> 2, acol0 = (ac0 & 3) * 8;
    const int ar1 = ac1 >> 2, acol1 = (ac1 & 3) * 8;
    // B tile 32x128 per plane: 512 chunks; chunk c: row = c>>4, col = (c&15)*8
    const int br0 = ac0 >> 4, bcol0 = (ac0 & 15) * 8;
    const int br1 = ac1 >> 4, bcol1 = (ac1 & 15) * 8;

    const __nv_bfloat16* a0p = A0 + (size_t)(brow + ar0) * K + acol0;
    const __nv_bfloat16* a1p = A0 + (size_t)(brow + ar1) * K + acol1;
    const __nv_bfloat16* a0q = A1 + (size_t)(brow + ar0) * K + acol0;
    const __nv_bfloat16* a1q = A1 + (size_t)(brow + ar1) * K + acol1;
    const __nv_bfloat16* b0p = B0 + (size_t)br0 * N + bcol + bcol0;
    const __nv_bfloat16* b1p = B0 + (size_t)br1 * N + bcol + bcol1;
    const __nv_bfloat16* b0q = B1 + (size_t)br0 * N + bcol + bcol0;
    const __nv_bfloat16* b1q = B1 + (size_t)br1 * N + bcol + bcol1;

    wmma::fragment<wmma::accumulator, 16, 16, 16, float> acc[4][2];
#pragma unroll
    for (int mi = 0; mi < 4; mi++)
#pragma unroll
        for (int ni = 0; ni < 2; ni++) wmma::fill_fragment(acc[mi][ni], 0.f);

    // prologue loads (8 x 16B per thread)
    uint4 rA0 = *(const uint4*)a0p, rA1 = *(const uint4*)a1p;
    uint4 rA2 = *(const uint4*)a0q, rA3 = *(const uint4*)a1q;
    uint4 rB0 = *(const uint4*)b0p, rB1 = *(const uint4*)b1p;
    uint4 rB2 = *(const uint4*)b0q, rB3 = *(const uint4*)b1q;
    a0p += KSTEP; a1p += KSTEP; a0q += KSTEP; a1q += KSTEP;
    b0p += (size_t)KSTEP * N; b1p += (size_t)KSTEP * N;
    b0q += (size_t)KSTEP * N; b1q += (size_t)KSTEP * N;

    for (int k0 = 0; k0 < K; k0 += KSTEP) {
        *(uint4*)&As[0][ar0][acol0] = rA0;
        *(uint4*)&As[0][ar1][acol1] = rA1;
        *(uint4*)&As[1][ar0][acol0] = rA2;
        *(uint4*)&As[1][ar1][acol1] = rA3;
        *(uint4*)&Bs[0][br0][bcol0] = rB0;
        *(uint4*)&Bs[0][br1][bcol1] = rB1;
        *(uint4*)&Bs[1][br0][bcol0] = rB2;
        *(uint4*)&Bs[1][br1][bcol1] = rB3;
        __syncthreads();

        if (k0 + KSTEP < K) {
            rA0 = *(const uint4*)a0p; rA1 = *(const uint4*)a1p;
            rA2 = *(const uint4*)a0q; rA3 = *(const uint4*)a1q;
            rB0 = *(const uint4*)b0p; rB1 = *(const uint4*)b1p;
            rB2 = *(const uint4*)b0q; rB3 = *(const uint4*)b1q;
            a0p += KSTEP; a1p += KSTEP; a0q += KSTEP; a1q += KSTEP;
            b0p += (size_t)KSTEP * N; b1p += (size_t)KSTEP * N;
            b0q += (size_t)KSTEP * N; b1q += (size_t)KSTEP * N;
        }

#pragma unroll
        for (int ks = 0; ks < KSTEP / 16; ks++) {
            wmma::fragment<wmma::matrix_b, 16, 16, 16, __nv_bfloat16, wmma::row_major> bf[2][2];
#pragma unroll
            for (int ni = 0; ni < 2; ni++) {
                wmma::load_matrix_sync(bf[ni][0], &Bs[0][ks * 16][wn + ni * 16], LDB);
                wmma::load_matrix_sync(bf[ni][1], &Bs[1][ks * 16][wn + ni * 16], LDB);
            }
#pragma unroll
            for (int mi = 0; mi < 4; mi++) {
                wmma::fragment<wmma::matrix_a, 16, 16, 16, __nv_bfloat16, wmma::row_major> af0, af1;
                wmma::load_matrix_sync(af0, &As[0][wm + mi * 16][ks * 16], LDA);
                wmma::load_matrix_sync(af1, &As[1][wm + mi * 16][ks * 16], LDA);
#pragma unroll
                for (int ni = 0; ni < 2; ni++) {
                    wmma::mma_sync(acc[mi][ni], af0, bf[ni][0], acc[mi][ni]);
                    wmma::mma_sync(acc[mi][ni], af0, bf[ni][1], acc[mi][ni]);
                    wmma::mma_sync(acc[mi][ni], af1, bf[ni][0], acc[mi][ni]);
                }
            }
        }
        __syncthreads();
    }

#pragma unroll
    for (int mi = 0; mi < 4; mi++) {
#pragma unroll
        for (int ni = 0; ni < 2; ni++) {
            int m0 = brow + wm + mi * 16;
            int c0 = bcol + wn + ni * 16;
            if (mode == 0) {
                wmma::store_matrix_sync(C + (size_t)m0 * N + c0, acc[mi][ni], N,
                                        wmma::mem_row_major);
            } else {
                int b = m0 >> 12;
                int t = m0 & (TT - 1);
                int n = c0 >> 6;
                int d = c0 & 63;
                float* cp = C + (((size_t)(b * NHEADS + n) * TT + t) * DPH + d);
                wmma::store_matrix_sync(cp, acc[mi][ni], DPH, wmma::mem_row_major);
            }
        }
    }
}

// ---------------------------------------------------------------------------
// LSH bucketize
// ---------------------------------------------------------------------------
__global__ __launch_bounds__(128)
void bucketize_k(const float* __restrict__ rot)
{
    __shared__ __align__(16) float rs[DPH * 64];
    const int tid = threadIdx.x;
    for (int x = tid; x < DPH * 64; x += 128) rs[x] = rot[x];
    __syncthreads();

    const int gid = blockIdx.x * 128 + tid;
    const int bh  = gid >> 12;
    const int t   = gid & (TT - 1);

    const float* qrow = g_qk + ((size_t)bh * TT + t) * DPH;

    u64 vals2[32];
#pragma unroll
    for (int x = 0; x < 32; x++) vals2[x] = 0ull;

    for (int d = 0; d < DPH; d++) {
        u64 qb = bcast2(qrow[d]);
        const u64* rr = (const u64*)(rs + d * 64);
#pragma unroll
        for (int x = 0; x < 32; x++) fma2(vals2[x], qb, rr[x]);
    }

    float vals[64];
#pragma unroll
    for (int x = 0; x < 32; x++) {
        float2 f = unpack2(vals2[x]);
        vals[2 * x] = f.x; vals[2 * x + 1] = f.y;
    }

#pragma unroll
    for (int h = 0; h < NHASH; h++) {
        float best = -INFINITY;
        int   bi   = 0;
#pragma unroll
        for (int idx = 0; idx < 64; idx++) {
            float vv = (idx < 32) ? vals[h * 32 + idx] : -vals[h * 32 + idx - 32];
            if (vv > best) { best = vv; bi = idx; }
        }
        g_bkt[((size_t)(bh * NHASH + h)) * TT + t] = (unsigned char)bi;
    }
}

// ---------------------------------------------------------------------------
// Stable counting sort per (bh, hash)
// ---------------------------------------------------------------------------
__global__ __launch_bounds__(128)
void sort_k()
{
    const int seg = blockIdx.x;
    const int tid = threadIdx.x;
    __shared__ int hist[NBUCK * 128];
    __shared__ int btot[NBUCK];

    const unsigned char* bk = g_bkt + (size_t)seg * TT;

    for (int x = tid; x < NBUCK * 128; x += 128) hist[x] = 0;
    __syncthreads();

    const int t0 = tid * 32;
    for (int j = 0; j < 32; j++) {
        int b = bk[t0 + j];
        hist[b * 128 + tid]++;
    }
    __syncthreads();

    if (tid < NBUCK) {
        int s = 0;
        for (int j = 0; j < 128; j++) s += hist[tid * 128 + j];
        btot[tid] = s;
    }
    __syncthreads();

    if (tid == 0) {
        int run = 0;
        for (int b = 0; b < NBUCK; b++) { int c = btot[b]; btot[b] = run; run += c; }
    }
    __syncthreads();

    if (tid < NBUCK) {
        int run = btot[tid];
        for (int j = 0; j < 128; j++) {
            int c = hist[tid * 128 + j];
            hist[tid * 128 + j] = run;
            run += c;
        }
    }
    __syncthreads();

    int* dst = g_st + (size_t)(seg >> 1) * (NHASH * TT) + (size_t)(seg & 1) * TT;
    for (int j = 0; j < 32; j++) {
        int t = t0 + j;
        int b = bk[t];
        int pos = hist[b * 128 + tid]++;
        dst[pos] = t;
    }
}

// ---------------------------------------------------------------------------
// Chunked LSH attention with one-chunk look-back.
// ---------------------------------------------------------------------------
__global__ __launch_bounds__(64)
void attn_k(const unsigned char* __restrict__ pad)
{
    const int c  = blockIdx.x;
    const int bh = blockIdx.y;
    const int i  = threadIdx.x;
    const int b  = bh >> 4;

    __shared__ __align__(16) float ks[WW][68];
    __shared__ __align__(16) float vs[WW][68];
    __shared__ int   tks[WW];
    __shared__ float pen[WW];

    const int* stb = g_st + (size_t)bh * (NHASH * TT);

    const int sq = c * WW + i;
    const int tq = stb[sq];

    u64 qp[32];
    {
        const u64* qrow = (const u64*)(g_qk + ((size_t)bh * TT + tq) * DPH);
#pragma unroll
        for (int x = 0; x < 32; x++) qp[x] = qrow[x];
    }

    float m = -INFINITY, l = 0.f;
    u64 accp[32];
#pragma unroll
    for (int d = 0; d < 32; d++) accp[d] = 0ull;

    for (int stg = 0; stg < 2; stg++) {
        const int kc = (stg == 0) ? c : ((c + CCHUNK - 1) & (CCHUNK - 1));
        const int sk = kc * WW + i;
        const int tk = stb[sk];

        {
            const float4* krow = (const float4*)(g_qk + ((size_t)bh * TT + tk) * DPH);
            const float4* vrow = (const float4*)(g_v  + ((size_t)bh * TT + tk) * DPH);
            float4 kr[16];
            float ss = 0.f;
#pragma unroll
            for (int x = 0; x < 16; x++) {
                kr[x] = krow[x];
                ss += kr[x].x * kr[x].x + kr[x].y * kr[x].y
                    + kr[x].z * kr[x].z + kr[x].w * kr[x].w;
            }
            float inv = 1.f / fmaxf(sqrtf(ss), 1e-6f);
#pragma unroll
            for (int x = 0; x < 16; x++) {
                *(float4*)&ks[i][4 * x] = make_float4(kr[x].x * inv, kr[x].y * inv,
                                                      kr[x].z * inv, kr[x].w * inv);
                *(float4*)&vs[i][4 * x] = vrow[x];
            }
            tks[i] = tk;
            pen[i] = pad[(size_t)b * TT + tk] ? -1e9f : 0.f;
        }
        __syncthreads();

        for (int j = 0; j < WW; j++) {
            const u64* kj = (const u64*)&ks[j][0];
            u64 s2 = 0ull;
#pragma unroll
            for (int x = 0; x < 32; x++) fma2(s2, qp[x], kj[x]);
            float2 sp = unpack2(s2);
            float s = (sp.x + sp.y) * 0.125f + pen[j];
            if (tq == tks[j]) s -= 1e5f;

            const u64* vj = (const u64*)&vs[j][0];
            if (s <= m) {
                float p = __expf(s - m);
                l += p;
                u64 pb = bcast2(p);
#pragma unroll
                for (int d = 0; d < 32; d++) fma2(accp[d], pb, vj[d]);
            } else {
                float sc = __expf(m - s);
                l = l * sc + 1.f;
                u64 scb = bcast2(sc);
#pragma unroll
                for (int d = 0; d < 32; d++) accp[d] = fma2o(accp[d], scb, vj[d]);
                m = s;
            }
        }
        __syncthreads();
    }

    const float lse  = m + __logf(l);
    const float invl = 1.f / l;
    const int   h    = sq >> 12;

    float* orow = g_o + (((size_t)(bh * NHASH + h)) * TT + tq) * DPH;
#pragma unroll
    for (int d = 0; d < 32; d++) {
        float2 f = unpack2(accp[d]);
        orow[2 * d]     = f.x * invl;
        orow[2 * d + 1] = f.y * invl;
    }
    g_lse[((size_t)(bh * NHASH + h)) * TT + tq] = lse;
}

// ---------------------------------------------------------------------------
// Combine hash rounds -> [b,t,n,d] into g_qk (reuse).
// ---------------------------------------------------------------------------
__global__ __launch_bounds__(256)
void combine_k()
{
    const size_t idx = (size_t)blockIdx.x * 256 + threadIdx.x;
    const int d   = (int)(idx & 63);
    const size_t row = idx >> 6;
    const int bh  = (int)(row >> 12);
    const int t   = (int)(row & (TT - 1));

    const float l0 = g_lse[((size_t)(bh * 2 + 0)) * TT + t];
    const float l1 = g_lse[((size_t)(bh * 2 + 1)) * TT + t];
    const float mm = fmaxf(l0, l1);
    const float e0 = __expf(l0 - mm), e1 = __expf(l1 - mm);
    const float inv = 1.f / (e0 + e1);

    const float v0 = g_o[(((size_t)(bh * 2 + 0)) * TT + t) * DPH + d];
    const float v1 = g_o[(((size_t)(bh * 2 + 1)) * TT + t) * DPH + d];

    const int b = bh >> 4, n = bh & 15;
    g_qk[(((size_t)(b * TT + t)) * NHEADS + n) * DPH + d] = (e0 * v0 + e1 * v1) * inv;
}

// ---------------------------------------------------------------------------
// Host entry
// ---------------------------------------------------------------------------
extern "C" void kernel_launch(void* const* d_in, const int* in_sizes, int n_in,
                              void* d_out, int out_size)
{
    const float*         x    = (const float*)d_in[0];
    const unsigned char* pad  = (const unsigned char*)d_in[1];
    const float*         wqk  = (const float*)d_in[2];
    const float*         wv   = (const float*)d_in[3];
    const float*         wo   = (const float*)d_in[4];
    const float*         rot  = (const float*)d_in[5];
    float*               out  = (float*)d_out;

    void *p_qk, *p_v, *p_ab0, *p_ab1, *p_wb0, *p_wb1;
    cudaGetSymbolAddress(&p_qk,  g_qk);
    cudaGetSymbolAddress(&p_v,   g_v);
    cudaGetSymbolAddress(&p_ab0, g_ab0);
    cudaGetSymbolAddress(&p_ab1, g_ab1);
    cudaGetSymbolAddress(&p_wb0, g_wb0);
    cudaGetSymbolAddress(&p_wb1, g_wb1);

    const int nx4 = MTOT * HID / 4;
    const int nw4 = HID * HID / 4;

    dim3 gg(HID / 128, MTOT / 128);

    // 1) qk projection: exact fp32 scalar (feeds LSH argmax)
    sgemm_qk_k<<<gg, 256>>>(x, wqk, (float*)p_qk, MTOT, HID, HID);

    // 2) v projection: hoisted bf16 split + tensor GEMM
    cvt2_k<<<(nx4 + 255) / 256, 256>>>(x, (__nv_bfloat16*)p_ab0, (__nv_bfloat16*)p_ab1, nx4);
    cvt2_k<<<(nw4 + 255) / 256, 256>>>(wv, (__nv_bfloat16*)p_wb0, (__nv_bfloat16*)p_wb1, nw4);
    tgemm_k<<<gg, 256>>>((__nv_bfloat16*)p_ab0, (__nv_bfloat16*)p_ab1,
                         (__nv_bfloat16*)p_wb0, (__nv_bfloat16*)p_wb1,
                         (float*)p_v, MTOT, HID, HID, 1);

    // 3) LSH bucketing + stable sort
    bucketize_k<<<(BH * TT) / 128, 128>>>(rot);
    sort_k<<<BH * NHASH, 128>>>();

    // 4) chunked attention
    dim3 ga(CCHUNK, BH);
    attn_k<<<ga, 64>>>(pad);

    // 5) combine -> [b,t,n,d] into g_qk
    combine_k<<<((size_t)BH * TT * DPH) / 256, 256>>>();

    // 6) output projection: hoisted split + tensor GEMM
    cvt2_k<<<(nx4 + 255) / 256, 256>>>((const float*)p_qk,
                                       (__nv_bfloat16*)p_ab0, (__nv_bfloat16*)p_ab1, nx4);
    cvt2_k<<<(nw4 + 255) / 256, 256>>>(wo, (__nv_bfloat16*)p_wb0, (__nv_bfloat16*)p_wb1, nw4);
    tgemm_k<<<gg, 256>>>((__nv_bfloat16*)p_ab0, (__nv_bfloat16*)p_ab1,
                         (__nv_bfloat16*)p_wb0, (__nv_bfloat16*)p_wb1,
                         out, MTOT, HID, HID, 0);
}

// round 12
// speedup vs baseline: 1.0238x; 1.0238x over previous
#include <cuda_runtime.h>
#include <cuda_bf16.h>
#include <mma.h>
#include <math.h>

using namespace nvcuda;

// ---------------------------------------------------------------------------
// Problem constants
// ---------------------------------------------------------------------------
#define TT      4096
#define NHEADS  16
#define BB      4
#define BH      64
#define DPH     64
#define HID     1024
#define NHASH   2
#define NBUCK   64
#define WW      64
#define CCHUNK  128
#define MTOT    16384

typedef unsigned long long u64;

// ---- packed fp32x2 helpers ------------------------------------------------
__device__ __forceinline__ void fma2(u64& d, u64 a, u64 b) {
    asm("fma.rn.f32x2 %0, %1, %2, %0;" : "+l"(d) : "l"(a), "l"(b));
}
__device__ __forceinline__ u64 fma2o(u64 a, u64 b, u64 c) {
    u64 d; asm("fma.rn.f32x2 %0, %1, %2, %3;" : "=l"(d) : "l"(a), "l"(b), "l"(c));
    return d;
}
__device__ __forceinline__ u64 bcast2(float f) {
    u64 r; unsigned int u = __float_as_uint(f);
    asm("mov.b64 %0, {%1, %1};" : "=l"(r) : "r"(u));
    return r;
}
__device__ __forceinline__ float2 unpack2(u64 v) {
    unsigned int lo, hi;
    asm("mov.b64 {%0, %1}, %2;" : "=r"(lo), "=r"(hi) : "l"(v));
    return make_float2(__uint_as_float(lo), __uint_as_float(hi));
}

// ---------------------------------------------------------------------------
// Device scratch (static).
// ---------------------------------------------------------------------------
__device__ float          g_qk  [(size_t)BH * TT * DPH];
__device__ float          g_v   [(size_t)BH * TT * DPH];
__device__ float          g_o   [(size_t)BH * NHASH * TT * DPH];
__device__ float          g_lse [(size_t)BH * NHASH * TT];
__device__ int            g_st  [(size_t)BH * NHASH * TT];
__device__ unsigned char  g_bkt [(size_t)BH * NHASH * TT];
__device__ __nv_bfloat16  g_ab0 [(size_t)MTOT * HID];   // 32 MB  A plane 0
__device__ __nv_bfloat16  g_ab1 [(size_t)MTOT * HID];   // 32 MB  A plane 1
__device__ __nv_bfloat16  g_wb0 [(size_t)HID * HID];    //  2 MB  B plane 0
__device__ __nv_bfloat16  g_wb1 [(size_t)HID * HID];    //  2 MB  B plane 1

// ---------------------------------------------------------------------------
// fp32 -> 2 bf16 planes (hi + residual).
// ---------------------------------------------------------------------------
__global__ __launch_bounds__(256)
void cvt2_k(const float* __restrict__ src, __nv_bfloat16* __restrict__ p0,
            __nv_bfloat16* __restrict__ p1, int n4)
{
    int i = blockIdx.x * 256 + threadIdx.x;
    if (i >= n4) return;
    float4 v = ((const float4*)src)[i];
    float va[4] = {v.x, v.y, v.z, v.w};
    __nv_bfloat16 t0[4], t1[4];
#pragma unroll
    for (int j = 0; j < 4; j++) {
        t0[j] = __float2bfloat16_rn(va[j]);
        t1[j] = __float2bfloat16_rn(va[j] - __bfloat162float(t0[j]));
    }
    ((uint2*)p0)[i] = *(uint2*)t0;
    ((uint2*)p1)[i] = *(uint2*)t1;
}

// ===========================================================================
// SCALAR fp32 SGEMM (exact; qk only -- feeds LSH argmax decisions).
// ===========================================================================
__global__ __launch_bounds__(256)
void sgemm_qk_k(const float* __restrict__ A, const float* __restrict__ B,
                float* __restrict__ C, int M, int N, int K)
{
    __shared__ __align__(16) float As[8][128];
    __shared__ __align__(16) float Bs[8][128];

    const int tid  = threadIdx.x;
    const int brow = blockIdx.y * 128;
    const int bcol = blockIdx.x * 128;
    const int tr   = (tid >> 4) * 8;
    const int tc   = (tid & 15) * 8;

    const int a_row = tid >> 1;
    const int a_col = (tid & 1) * 4;
    const int b_row = tid >> 5;
    const int b_col = (tid & 31) * 4;

    const float* Ap = A + (size_t)(brow + a_row) * K + a_col;
    const float* Bp = B + (size_t)b_row * N + bcol + b_col;

    float acc[8][8];
#pragma unroll
    for (int y = 0; y < 8; y++)
#pragma unroll
        for (int x = 0; x < 8; x++) acc[y][x] = 0.f;

    float4 av = *(const float4*)Ap;  Ap += 8;
    float4 bv = *(const float4*)Bp;  Bp += (size_t)8 * N;

    for (int k0 = 0; k0 < K; k0 += 8) {
        As[a_col + 0][a_row] = av.x;
        As[a_col + 1][a_row] = av.y;
        As[a_col + 2][a_row] = av.z;
        As[a_col + 3][a_row] = av.w;
        *(float4*)&Bs[b_row][b_col] = bv;
        __syncthreads();

        if (k0 + 8 < K) {
            av = *(const float4*)Ap;  Ap += 8;
            bv = *(const float4*)Bp;  Bp += (size_t)8 * N;
        }

#pragma unroll
        for (int kk = 0; kk < 8; kk++) {
            float4 a0 = *(const float4*)&As[kk][tr];
            float4 a1 = *(const float4*)&As[kk][tr + 4];
            float4 b0 = *(const float4*)&Bs[kk][tc];
            float4 b1 = *(const float4*)&Bs[kk][tc + 4];
            float ar[8] = {a0.x, a0.y, a0.z, a0.w, a1.x, a1.y, a1.z, a1.w};
            float br[8] = {b0.x, b0.y, b0.z, b0.w, b1.x, b1.y, b1.z, b1.w};
#pragma unroll
            for (int y = 0; y < 8; y++)
#pragma unroll
                for (int x = 0; x < 8; x++) acc[y][x] += ar[y] * br[x];
        }
        __syncthreads();
    }

#pragma unroll
    for (int y = 0; y < 8; y++) {
        int m = brow + tr + y;
        int b = m >> 12;
        int t = m & (TT - 1);
        int col0 = bcol + tc;
        int n = col0 >> 6;
        int d = col0 & 63;
        float* cp = C + (((size_t)(b * NHEADS + n) * TT + t) * DPH + d);
        *(float4*)(cp)     = make_float4(acc[y][0], acc[y][1], acc[y][2], acc[y][3]);
        *(float4*)(cp + 4) = make_float4(acc[y][4], acc[y][5], acc[y][6], acc[y][7]);
    }
}

// ===========================================================================
// bf16 tensor GEMM on pre-split planes: D = A0B0 + A0B1 + A1B0.
// LDA=40 elems (80B): ldmatrix row offsets mod 128B all distinct ->
// conflict-free A-fragment loads (LDA=48 was 2-way conflicted).
// ===========================================================================
#define KSTEP 32
#define LDA   40    // 32 + 8 pad elems (80B rows; conflict-free LDSM)
#define LDB   136   // 128 + 8 pad elems (272B rows; conflict-free)

static_assert((2 * 128 * LDA + 2 * KSTEP * LDB) * 2 <= 48 * 1024, "smem");

__global__ __launch_bounds__(256)
void tgemm_k(const __nv_bfloat16* __restrict__ A0, const __nv_bfloat16* __restrict__ A1,
             const __nv_bfloat16* __restrict__ B0, const __nv_bfloat16* __restrict__ B1,
             float* __restrict__ C, int M, int N, int K, int mode)
{
    __shared__ __align__(32) __nv_bfloat16 As[2][128][LDA];
    __shared__ __align__(32) __nv_bfloat16 Bs[2][KSTEP][LDB];

    const int tid  = threadIdx.x;
    const int wid  = tid >> 5;
    const int brow = blockIdx.y * 128;
    const int bcol = blockIdx.x * 128;
    const int wm   = (wid >> 2) * 64;
    const int wn   = (wid & 3) * 32;

    const int ac0 = tid, ac1 = tid + 256;
    const int ar0 = ac0 >> 2, acol0 = (ac0 & 3) * 8;
    const int ar1 = ac1 >> 2, acol1 = (ac1 & 3) * 8;
    const int br0 = ac0 >> 4, bcol0 = (ac0 & 15) * 8;
    const int br1 = ac1 >> 4, bcol1 = (ac1 & 15) * 8;

    const __nv_bfloat16* a0p = A0 + (size_t)(brow + ar0) * K + acol0;
    const __nv_bfloat16* a1p = A0 + (size_t)(brow + ar1) * K + acol1;
    const __nv_bfloat16* a0q = A1 + (size_t)(brow + ar0) * K + acol0;
    const __nv_bfloat16* a1q = A1 + (size_t)(brow + ar1) * K + acol1;
    const __nv_bfloat16* b0p = B0 + (size_t)br0 * N + bcol + bcol0;
    const __nv_bfloat16* b1p = B0 + (size_t)br1 * N + bcol + bcol1;
    const __nv_bfloat16* b0q = B1 + (size_t)br0 * N + bcol + bcol0;
    const __nv_bfloat16* b1q = B1 + (size_t)br1 * N + bcol + bcol1;

    wmma::fragment<wmma::accumulator, 16, 16, 16, float> acc[4][2];
#pragma unroll
    for (int mi = 0; mi < 4; mi++)
#pragma unroll
        for (int ni = 0; ni < 2; ni++) wmma::fill_fragment(acc[mi][ni], 0.f);

    uint4 rA0 = *(const uint4*)a0p, rA1 = *(const uint4*)a1p;
    uint4 rA2 = *(const uint4*)a0q, rA3 = *(const uint4*)a1q;
    uint4 rB0 = *(const uint4*)b0p, rB1 = *(const uint4*)b1p;
    uint4 rB2 = *(const uint4*)b0q, rB3 = *(const uint4*)b1q;
    a0p += KSTEP; a1p += KSTEP; a0q += KSTEP; a1q += KSTEP;
    b0p += (size_t)KSTEP * N; b1p += (size_t)KSTEP * N;
    b0q += (size_t)KSTEP * N; b1q += (size_t)KSTEP * N;

    for (int k0 = 0; k0 < K; k0 += KSTEP) {
        *(uint4*)&As[0][ar0][acol0] = rA0;
        *(uint4*)&As[0][ar1][acol1] = rA1;
        *(uint4*)&As[1][ar0][acol0] = rA2;
        *(uint4*)&As[1][ar1][acol1] = rA3;
        *(uint4*)&Bs[0][br0][bcol0] = rB0;
        *(uint4*)&Bs[0][br1][bcol1] = rB1;
        *(uint4*)&Bs[1][br0][bcol0] = rB2;
        *(uint4*)&Bs[1][br1][bcol1] = rB3;
        __syncthreads();

        if (k0 + KSTEP < K) {
            rA0 = *(const uint4*)a0p; rA1 = *(const uint4*)a1p;
            rA2 = *(const uint4*)a0q; rA3 = *(const uint4*)a1q;
            rB0 = *(const uint4*)b0p; rB1 = *(const uint4*)b1p;
            rB2 = *(const uint4*)b0q; rB3 = *(const uint4*)b1q;
            a0p += KSTEP; a1p += KSTEP; a0q += KSTEP; a1q += KSTEP;
            b0p += (size_t)KSTEP * N; b1p += (size_t)KSTEP * N;
            b0q += (size_t)KSTEP * N; b1q += (size_t)KSTEP * N;
        }

#pragma unroll
        for (int ks = 0; ks < KSTEP / 16; ks++) {
            wmma::fragment<wmma::matrix_b, 16, 16, 16, __nv_bfloat16, wmma::row_major> bf[2][2];
#pragma unroll
            for (int ni = 0; ni < 2; ni++) {
                wmma::load_matrix_sync(bf[ni][0], &Bs[0][ks * 16][wn + ni * 16], LDB);
                wmma::load_matrix_sync(bf[ni][1], &Bs[1][ks * 16][wn + ni * 16], LDB);
            }
#pragma unroll
            for (int mi = 0; mi < 4; mi++) {
                wmma::fragment<wmma::matrix_a, 16, 16, 16, __nv_bfloat16, wmma::row_major> af0, af1;
                wmma::load_matrix_sync(af0, &As[0][wm + mi * 16][ks * 16], LDA);
                wmma::load_matrix_sync(af1, &As[1][wm + mi * 16][ks * 16], LDA);
#pragma unroll
                for (int ni = 0; ni < 2; ni++) {
                    wmma::mma_sync(acc[mi][ni], af0, bf[ni][0], acc[mi][ni]);
                    wmma::mma_sync(acc[mi][ni], af0, bf[ni][1], acc[mi][ni]);
                    wmma::mma_sync(acc[mi][ni], af1, bf[ni][0], acc[mi][ni]);
                }
            }
        }
        __syncthreads();
    }

#pragma unroll
    for (int mi = 0; mi < 4; mi++) {
#pragma unroll
        for (int ni = 0; ni < 2; ni++) {
            int m0 = brow + wm + mi * 16;
            int c0 = bcol + wn + ni * 16;
            if (mode == 0) {
                wmma::store_matrix_sync(C + (size_t)m0 * N + c0, acc[mi][ni], N,
                                        wmma::mem_row_major);
            } else {
                int b = m0 >> 12;
                int t = m0 & (TT - 1);
                int n = c0 >> 6;
                int d = c0 & 63;
                float* cp = C + (((size_t)(b * NHEADS + n) * TT + t) * DPH + d);
                wmma::store_matrix_sync(cp, acc[mi][ni], DPH, wmma::mem_row_major);
            }
        }
    }
}

// ---------------------------------------------------------------------------
// LSH bucketize
// ---------------------------------------------------------------------------
__global__ __launch_bounds__(128)
void bucketize_k(const float* __restrict__ rot)
{
    __shared__ __align__(16) float rs[DPH * 64];
    const int tid = threadIdx.x;
    for (int x = tid; x < DPH * 64; x += 128) rs[x] = rot[x];
    __syncthreads();

    const int gid = blockIdx.x * 128 + tid;
    const int bh  = gid >> 12;
    const int t   = gid & (TT - 1);

    const float* qrow = g_qk + ((size_t)bh * TT + t) * DPH;

    u64 vals2[32];
#pragma unroll
    for (int x = 0; x < 32; x++) vals2[x] = 0ull;

    for (int d = 0; d < DPH; d++) {
        u64 qb = bcast2(qrow[d]);
        const u64* rr = (const u64*)(rs + d * 64);
#pragma unroll
        for (int x = 0; x < 32; x++) fma2(vals2[x], qb, rr[x]);
    }

    float vals[64];
#pragma unroll
    for (int x = 0; x < 32; x++) {
        float2 f = unpack2(vals2[x]);
        vals[2 * x] = f.x; vals[2 * x + 1] = f.y;
    }

#pragma unroll
    for (int h = 0; h < NHASH; h++) {
        float best = -INFINITY;
        int   bi   = 0;
#pragma unroll
        for (int idx = 0; idx < 64; idx++) {
            float vv = (idx < 32) ? vals[h * 32 + idx] : -vals[h * 32 + idx - 32];
            if (vv > best) { best = vv; bi = idx; }
        }
        g_bkt[((size_t)(bh * NHASH + h)) * TT + t] = (unsigned char)bi;
    }
}

// ---------------------------------------------------------------------------
// Stable counting sort per (bh, hash)
// ---------------------------------------------------------------------------
__global__ __launch_bounds__(128)
void sort_k()
{
    const int seg = blockIdx.x;
    const int tid = threadIdx.x;
    __shared__ int hist[NBUCK * 128];
    __shared__ int btot[NBUCK];

    const unsigned char* bk = g_bkt + (size_t)seg * TT;

    for (int x = tid; x < NBUCK * 128; x += 128) hist[x] = 0;
    __syncthreads();

    const int t0 = tid * 32;
    for (int j = 0; j < 32; j++) {
        int b = bk[t0 + j];
        hist[b * 128 + tid]++;
    }
    __syncthreads();

    if (tid < NBUCK) {
        int s = 0;
        for (int j = 0; j < 128; j++) s += hist[tid * 128 + j];
        btot[tid] = s;
    }
    __syncthreads();

    if (tid == 0) {
        int run = 0;
        for (int b = 0; b < NBUCK; b++) { int c = btot[b]; btot[b] = run; run += c; }
    }
    __syncthreads();

    if (tid < NBUCK) {
        int run = btot[tid];
        for (int j = 0; j < 128; j++) {
            int c = hist[tid * 128 + j];
            hist[tid * 128 + j] = run;
            run += c;
        }
    }
    __syncthreads();

    int* dst = g_st + (size_t)(seg >> 1) * (NHASH * TT) + (size_t)(seg & 1) * TT;
    for (int j = 0; j < 32; j++) {
        int t = t0 + j;
        int b = bk[t];
        int pos = hist[b * 128 + tid]++;
        dst[pos] = t;
    }
}

// ---------------------------------------------------------------------------
// Chunked LSH attention with one-chunk look-back.
// ---------------------------------------------------------------------------
__global__ __launch_bounds__(64)
void attn_k(const unsigned char* __restrict__ pad)
{
    const int c  = blockIdx.x;
    const int bh = blockIdx.y;
    const int i  = threadIdx.x;
    const int b  = bh >> 4;

    __shared__ __align__(16) float ks[WW][68];
    __shared__ __align__(16) float vs[WW][68];
    __shared__ int   tks[WW];
    __shared__ float pen[WW];

    const int* stb = g_st + (size_t)bh * (NHASH * TT);

    const int sq = c * WW + i;
    const int tq = stb[sq];

    u64 qp[32];
    {
        const u64* qrow = (const u64*)(g_qk + ((size_t)bh * TT + tq) * DPH);
#pragma unroll
        for (int x = 0; x < 32; x++) qp[x] = qrow[x];
    }

    float m = -INFINITY, l = 0.f;
    u64 accp[32];
#pragma unroll
    for (int d = 0; d < 32; d++) accp[d] = 0ull;

    for (int stg = 0; stg < 2; stg++) {
        const int kc = (stg == 0) ? c : ((c + CCHUNK - 1) & (CCHUNK - 1));
        const int sk = kc * WW + i;
        const int tk = stb[sk];

        {
            const float4* krow = (const float4*)(g_qk + ((size_t)bh * TT + tk) * DPH);
            const float4* vrow = (const float4*)(g_v  + ((size_t)bh * TT + tk) * DPH);
            float4 kr[16];
            float ss = 0.f;
#pragma unroll
            for (int x = 0; x < 16; x++) {
                kr[x] = krow[x];
                ss += kr[x].x * kr[x].x + kr[x].y * kr[x].y
                    + kr[x].z * kr[x].z + kr[x].w * kr[x].w;
            }
            float inv = 1.f / fmaxf(sqrtf(ss), 1e-6f);
#pragma unroll
            for (int x = 0; x < 16; x++) {
                *(float4*)&ks[i][4 * x] = make_float4(kr[x].x * inv, kr[x].y * inv,
                                                      kr[x].z * inv, kr[x].w * inv);
                *(float4*)&vs[i][4 * x] = vrow[x];
            }
            tks[i] = tk;
            pen[i] = pad[(size_t)b * TT + tk] ? -1e9f : 0.f;
        }
        __syncthreads();

        for (int j = 0; j < WW; j++) {
            const u64* kj = (const u64*)&ks[j][0];
            u64 s2 = 0ull;
#pragma unroll
            for (int x = 0; x < 32; x++) fma2(s2, qp[x], kj[x]);
            float2 sp = unpack2(s2);
            float s = (sp.x + sp.y) * 0.125f + pen[j];
            if (tq == tks[j]) s -= 1e5f;

            const u64* vj = (const u64*)&vs[j][0];
            if (s <= m) {
                float p = __expf(s - m);
                l += p;
                u64 pb = bcast2(p);
#pragma unroll
                for (int d = 0; d < 32; d++) fma2(accp[d], pb, vj[d]);
            } else {
                float sc = __expf(m - s);
                l = l * sc + 1.f;
                u64 scb = bcast2(sc);
#pragma unroll
                for (int d = 0; d < 32; d++) accp[d] = fma2o(accp[d], scb, vj[d]);
                m = s;
            }
        }
        __syncthreads();
    }

    const float lse  = m + __logf(l);
    const float invl = 1.f / l;
    const int   h    = sq >> 12;

    float* orow = g_o + (((size_t)(bh * NHASH + h)) * TT + tq) * DPH;
#pragma unroll
    for (int d = 0; d < 32; d++) {
        float2 f = unpack2(accp[d]);
        orow[2 * d]     = f.x * invl;
        orow[2 * d + 1] = f.y * invl;
    }
    g_lse[((size_t)(bh * NHASH + h)) * TT + tq] = lse;
}

// ---------------------------------------------------------------------------
// Combine hash rounds; FUSED bf16 split epilogue: writes the A-operand
// planes for the output projection directly (no f32 comb, no cvt pass).
// Each thread handles a pair of d values.
// ---------------------------------------------------------------------------
__global__ __launch_bounds__(256)
void combine_k()
{
    const size_t idx = (size_t)blockIdx.x * 256 + threadIdx.x; // BH*T*DPH/2
    const int d2  = (int)(idx & 31);          // pair index, d = 2*d2
    const size_t row = idx >> 5;              // bh*T + t
    const int bh  = (int)(row >> 12);
    const int t   = (int)(row & (TT - 1));

    const float l0 = g_lse[((size_t)(bh * 2 + 0)) * TT + t];
    const float l1 = g_lse[((size_t)(bh * 2 + 1)) * TT + t];
    const float mm = fmaxf(l0, l1);
    const float e0 = __expf(l0 - mm), e1 = __expf(l1 - mm);
    const float inv = 1.f / (e0 + e1);

    const float2 v0 = ((const float2*)g_o)[(((size_t)(bh * 2 + 0)) * TT + t) * 32 + d2];
    const float2 v1 = ((const float2*)g_o)[(((size_t)(bh * 2 + 1)) * TT + t) * 32 + d2];

    const float r0 = (e0 * v0.x + e1 * v1.x) * inv;
    const float r1 = (e0 * v0.y + e1 * v1.y) * inv;

    __nv_bfloat16 h0 = __float2bfloat16_rn(r0);
    __nv_bfloat16 h1 = __float2bfloat16_rn(r1);
    __nv_bfloat16 q0 = __float2bfloat16_rn(r0 - __bfloat162float(h0));
    __nv_bfloat16 q1 = __float2bfloat16_rn(r1 - __bfloat162float(h1));

    const int b = bh >> 4, n = bh & 15;
    const size_t o = (((size_t)(b * TT + t)) * NHEADS + n) * 32 + d2;  // uint units
    ((unsigned*)g_ab0)[o] = (unsigned)__bfloat16_as_ushort(h0)
                          | ((unsigned)__bfloat16_as_ushort(h1) << 16);
    ((unsigned*)g_ab1)[o] = (unsigned)__bfloat16_as_ushort(q0)
                          | ((unsigned)__bfloat16_as_ushort(q1) << 16);
}

// ---------------------------------------------------------------------------
// Host entry
// ---------------------------------------------------------------------------
extern "C" void kernel_launch(void* const* d_in, const int* in_sizes, int n_in,
                              void* d_out, int out_size)
{
    const float*         x    = (const float*)d_in[0];
    const unsigned char* pad  = (const unsigned char*)d_in[1];
    const float*         wqk  = (const float*)d_in[2];
    const float*         wv   = (const float*)d_in[3];
    const float*         wo   = (const float*)d_in[4];
    const float*         rot  = (const float*)d_in[5];
    float*               out  = (float*)d_out;

    void *p_qk, *p_v, *p_ab0, *p_ab1, *p_wb0, *p_wb1;
    cudaGetSymbolAddress(&p_qk,  g_qk);
    cudaGetSymbolAddress(&p_v,   g_v);
    cudaGetSymbolAddress(&p_ab0, g_ab0);
    cudaGetSymbolAddress(&p_ab1, g_ab1);
    cudaGetSymbolAddress(&p_wb0, g_wb0);
    cudaGetSymbolAddress(&p_wb1, g_wb1);

    const int nx4 = MTOT * HID / 4;
    const int nw4 = HID * HID / 4;

    dim3 gg(HID / 128, MTOT / 128);

    // 1) qk projection: exact fp32 scalar (feeds LSH argmax)
    sgemm_qk_k<<<gg, 256>>>(x, wqk, (float*)p_qk, MTOT, HID, HID);

    // 2) v projection: hoisted bf16 split + tensor GEMM
    cvt2_k<<<(nx4 + 255) / 256, 256>>>(x, (__nv_bfloat16*)p_ab0, (__nv_bfloat16*)p_ab1, nx4);
    cvt2_k<<<(nw4 + 255) / 256, 256>>>(wv, (__nv_bfloat16*)p_wb0, (__nv_bfloat16*)p_wb1, nw4);
    tgemm_k<<<gg, 256>>>((__nv_bfloat16*)p_ab0, (__nv_bfloat16*)p_ab1,
                         (__nv_bfloat16*)p_wb0, (__nv_bfloat16*)p_wb1,
                         (float*)p_v, MTOT, HID, HID, 1);

    // 3) LSH bucketing + stable sort
    bucketize_k<<<(BH * TT) / 128, 128>>>(rot);
    sort_k<<<BH * NHASH, 128>>>();

    // 4) chunked attention
    dim3 ga(CCHUNK, BH);
    attn_k<<<ga, 64>>>(pad);

    // 5) combine -> bf16 A-planes directly (fused split epilogue)
    combine_k<<<((size_t)BH * TT * DPH / 2) / 256, 256>>>();

    // 6) output projection: tensor GEMM on fused planes
    cvt2_k<<<(nw4 + 255) / 256, 256>>>(wo, (__nv_bfloat16*)p_wb0, (__nv_bfloat16*)p_wb1, nw4);
    tgemm_k<<<gg, 256>>>((__nv_bfloat16*)p_ab0, (__nv_bfloat16*)p_ab1,
                         (__nv_bfloat16*)p_wb0, (__nv_bfloat16*)p_wb1,
                         out, MTOT, HID, HID, 0);
}

// round 13
// speedup vs baseline: 1.0810x; 1.0558x over previous
#include <cuda_runtime.h>
#include <cuda_bf16.h>
#include <mma.h>
#include <math.h>

using namespace nvcuda;

// ---------------------------------------------------------------------------
// Problem constants
// ---------------------------------------------------------------------------
#define TT      4096
#define NHEADS  16
#define BB      4
#define BH      64
#define DPH     64
#define HID     1024
#define NHASH   2
#define NBUCK   64
#define WW      64
#define CCHUNK  128
#define MTOT    16384

typedef unsigned long long u64;

// ---- packed fp32x2 helpers ------------------------------------------------
__device__ __forceinline__ void fma2(u64& d, u64 a, u64 b) {
    asm("fma.rn.f32x2 %0, %1, %2, %0;" : "+l"(d) : "l"(a), "l"(b));
}
__device__ __forceinline__ u64 fma2o(u64 a, u64 b, u64 c) {
    u64 d; asm("fma.rn.f32x2 %0, %1, %2, %3;" : "=l"(d) : "l"(a), "l"(b), "l"(c));
    return d;
}
__device__ __forceinline__ u64 bcast2(float f) {
    u64 r; unsigned int u = __float_as_uint(f);
    asm("mov.b64 %0, {%1, %1};" : "=l"(r) : "r"(u));
    return r;
}
__device__ __forceinline__ float2 unpack2(u64 v) {
    unsigned int lo, hi;
    asm("mov.b64 {%0, %1}, %2;" : "=r"(lo), "=r"(hi) : "l"(v));
    return make_float2(__uint_as_float(lo), __uint_as_float(hi));
}

// ---- cp.async helpers -----------------------------------------------------
__device__ __forceinline__ void cp16(void* smem, const void* gmem) {
    unsigned saddr = (unsigned)__cvta_generic_to_shared(smem);
    asm volatile("cp.async.cg.shared.global [%0], [%1], 16;"
                 :: "r"(saddr), "l"(gmem));
}
__device__ __forceinline__ void cp_commit() {
    asm volatile("cp.async.commit_group;");
}
template <int N>
__device__ __forceinline__ void cp_wait() {
    asm volatile("cp.async.wait_group %0;" :: "n"(N));
}

// ---------------------------------------------------------------------------
// Device scratch (static).
// ---------------------------------------------------------------------------
__device__ float          g_qk  [(size_t)BH * TT * DPH];
__device__ float          g_v   [(size_t)BH * TT * DPH];
__device__ float          g_o   [(size_t)BH * NHASH * TT * DPH];
__device__ float          g_lse [(size_t)BH * NHASH * TT];
__device__ int            g_st  [(size_t)BH * NHASH * TT];
__device__ unsigned char  g_bkt [(size_t)BH * NHASH * TT];
__device__ __nv_bfloat16  g_ab0 [(size_t)MTOT * HID];
__device__ __nv_bfloat16  g_ab1 [(size_t)MTOT * HID];
__device__ __nv_bfloat16  g_wb0 [(size_t)HID * HID];
__device__ __nv_bfloat16  g_wb1 [(size_t)HID * HID];

// ---------------------------------------------------------------------------
// fp32 -> 2 bf16 planes (hi + residual).
// ---------------------------------------------------------------------------
__global__ __launch_bounds__(256)
void cvt2_k(const float* __restrict__ src, __nv_bfloat16* __restrict__ p0,
            __nv_bfloat16* __restrict__ p1, int n4)
{
    int i = blockIdx.x * 256 + threadIdx.x;
    if (i >= n4) return;
    float4 v = ((const float4*)src)[i];
    float va[4] = {v.x, v.y, v.z, v.w};
    __nv_bfloat16 t0[4], t1[4];
#pragma unroll
    for (int j = 0; j < 4; j++) {
        t0[j] = __float2bfloat16_rn(va[j]);
        t1[j] = __float2bfloat16_rn(va[j] - __bfloat162float(t0[j]));
    }
    ((uint2*)p0)[i] = *(uint2*)t0;
    ((uint2*)p1)[i] = *(uint2*)t1;
}

// ===========================================================================
// SCALAR fp32 SGEMM (exact; qk only -- feeds LSH argmax decisions).
// ===========================================================================
__global__ __launch_bounds__(256)
void sgemm_qk_k(const float* __restrict__ A, const float* __restrict__ B,
                float* __restrict__ C, int M, int N, int K)
{
    __shared__ __align__(16) float As[8][128];
    __shared__ __align__(16) float Bs[8][128];

    const int tid  = threadIdx.x;
    const int brow = blockIdx.y * 128;
    const int bcol = blockIdx.x * 128;
    const int tr   = (tid >> 4) * 8;
    const int tc   = (tid & 15) * 8;

    const int a_row = tid >> 1;
    const int a_col = (tid & 1) * 4;
    const int b_row = tid >> 5;
    const int b_col = (tid & 31) * 4;

    const float* Ap = A + (size_t)(brow + a_row) * K + a_col;
    const float* Bp = B + (size_t)b_row * N + bcol + b_col;

    float acc[8][8];
#pragma unroll
    for (int y = 0; y < 8; y++)
#pragma unroll
        for (int x = 0; x < 8; x++) acc[y][x] = 0.f;

    float4 av = *(const float4*)Ap;  Ap += 8;
    float4 bv = *(const float4*)Bp;  Bp += (size_t)8 * N;

    for (int k0 = 0; k0 < K; k0 += 8) {
        As[a_col + 0][a_row] = av.x;
        As[a_col + 1][a_row] = av.y;
        As[a_col + 2][a_row] = av.z;
        As[a_col + 3][a_row] = av.w;
        *(float4*)&Bs[b_row][b_col] = bv;
        __syncthreads();

        if (k0 + 8 < K) {
            av = *(const float4*)Ap;  Ap += 8;
            bv = *(const float4*)Bp;  Bp += (size_t)8 * N;
        }

#pragma unroll
        for (int kk = 0; kk < 8; kk++) {
            float4 a0 = *(const float4*)&As[kk][tr];
            float4 a1 = *(const float4*)&As[kk][tr + 4];
            float4 b0 = *(const float4*)&Bs[kk][tc];
            float4 b1 = *(const float4*)&Bs[kk][tc + 4];
            float ar[8] = {a0.x, a0.y, a0.z, a0.w, a1.x, a1.y, a1.z, a1.w};
            float br[8] = {b0.x, b0.y, b0.z, b0.w, b1.x, b1.y, b1.z, b1.w};
#pragma unroll
            for (int y = 0; y < 8; y++)
#pragma unroll
                for (int x = 0; x < 8; x++) acc[y][x] += ar[y] * br[x];
        }
        __syncthreads();
    }

#pragma unroll
    for (int y = 0; y < 8; y++) {
        int m = brow + tr + y;
        int b = m >> 12;
        int t = m & (TT - 1);
        int col0 = bcol + tc;
        int n = col0 >> 6;
        int d = col0 & 63;
        float* cp = C + (((size_t)(b * NHEADS + n) * TT + t) * DPH + d);
        *(float4*)(cp)     = make_float4(acc[y][0], acc[y][1], acc[y][2], acc[y][3]);
        *(float4*)(cp + 4) = make_float4(acc[y][4], acc[y][5], acc[y][6], acc[y][7]);
    }
}

// ===========================================================================
// bf16 tensor GEMM, pre-split planes, 2-stage cp.async pipeline.
// D = A0B0 + A0B1 + A1B0.  KSTEP=16; LDA=24 elems (48B rows: conflict-free,
// 16B multiple); LDB=136. 128x128 tile, 8 warps (64x32 warp tiles).
// ===========================================================================
#define KSTEP 16
#define LDA   24
#define LDB   136

static_assert((2 * 2 * 128 * LDA + 2 * 2 * KSTEP * LDB) * 2 <= 48 * 1024, "smem");

__global__ __launch_bounds__(256)
void tgemm_k(const __nv_bfloat16* __restrict__ A0, const __nv_bfloat16* __restrict__ A1,
             const __nv_bfloat16* __restrict__ B0, const __nv_bfloat16* __restrict__ B1,
             float* __restrict__ C, int M, int N, int K, int mode)
{
    __shared__ __align__(32) __nv_bfloat16 As[2][2][128][LDA];   // [stage][plane]
    __shared__ __align__(32) __nv_bfloat16 Bs[2][2][KSTEP][LDB];

    const int tid  = threadIdx.x;
    const int wid  = tid >> 5;
    const int brow = blockIdx.y * 128;
    const int bcol = blockIdx.x * 128;
    const int wm   = (wid >> 2) * 64;
    const int wn   = (wid & 3) * 32;

    // A: 128x16 per plane = 256 8-elem chunks -> 1 chunk/thread/plane
    const int a_row = tid >> 1, a_col = (tid & 1) * 8;
    // B: 16x128 per plane = 256 chunks
    const int b_row = tid >> 4, b_col = (tid & 15) * 8;

    const __nv_bfloat16* a0g = A0 + (size_t)(brow + a_row) * K + a_col;
    const __nv_bfloat16* a1g = A1 + (size_t)(brow + a_row) * K + a_col;
    const __nv_bfloat16* b0g = B0 + (size_t)b_row * N + bcol + b_col;
    const __nv_bfloat16* b1g = B1 + (size_t)b_row * N + bcol + b_col;

    wmma::fragment<wmma::accumulator, 16, 16, 16, float> acc[4][2];
#pragma unroll
    for (int mi = 0; mi < 4; mi++)
#pragma unroll
        for (int ni = 0; ni < 2; ni++) wmma::fill_fragment(acc[mi][ni], 0.f);

    const int nIter = K / KSTEP;

    // prologue: stage 0 loads
    cp16(&As[0][0][a_row][a_col], a0g);
    cp16(&As[0][1][a_row][a_col], a1g);
    cp16(&Bs[0][0][b_row][b_col], b0g);
    cp16(&Bs[0][1][b_row][b_col], b1g);
    cp_commit();

    for (int i = 0; i < nIter; i++) {
        const int stg = i & 1;

        if (i + 1 < nIter) {
            const int nk = (i + 1) * KSTEP;
            const int ns = stg ^ 1;
            cp16(&As[ns][0][a_row][a_col], a0g + nk);
            cp16(&As[ns][1][a_row][a_col], a1g + nk);
            cp16(&Bs[ns][0][b_row][b_col], b0g + (size_t)nk * N);
            cp16(&Bs[ns][1][b_row][b_col], b1g + (size_t)nk * N);
            cp_commit();
            cp_wait<1>();
        } else {
            cp_wait<0>();
        }
        __syncthreads();

        wmma::fragment<wmma::matrix_b, 16, 16, 16, __nv_bfloat16, wmma::row_major> bf[2][2];
#pragma unroll
        for (int ni = 0; ni < 2; ni++) {
            wmma::load_matrix_sync(bf[ni][0], &Bs[stg][0][0][wn + ni * 16], LDB);
            wmma::load_matrix_sync(bf[ni][1], &Bs[stg][1][0][wn + ni * 16], LDB);
        }
#pragma unroll
        for (int mi = 0; mi < 4; mi++) {
            wmma::fragment<wmma::matrix_a, 16, 16, 16, __nv_bfloat16, wmma::row_major> af0, af1;
            wmma::load_matrix_sync(af0, &As[stg][0][wm + mi * 16][0], LDA);
            wmma::load_matrix_sync(af1, &As[stg][1][wm + mi * 16][0], LDA);
#pragma unroll
            for (int ni = 0; ni < 2; ni++) {
                wmma::mma_sync(acc[mi][ni], af0, bf[ni][0], acc[mi][ni]);
                wmma::mma_sync(acc[mi][ni], af0, bf[ni][1], acc[mi][ni]);
                wmma::mma_sync(acc[mi][ni], af1, bf[ni][0], acc[mi][ni]);
            }
        }
        __syncthreads();
    }

#pragma unroll
    for (int mi = 0; mi < 4; mi++) {
#pragma unroll
        for (int ni = 0; ni < 2; ni++) {
            int m0 = brow + wm + mi * 16;
            int c0 = bcol + wn + ni * 16;
            if (mode == 0) {
                wmma::store_matrix_sync(C + (size_t)m0 * N + c0, acc[mi][ni], N,
                                        wmma::mem_row_major);
            } else {
                int b = m0 >> 12;
                int t = m0 & (TT - 1);
                int n = c0 >> 6;
                int d = c0 & 63;
                float* cp = C + (((size_t)(b * NHEADS + n) * TT + t) * DPH + d);
                wmma::store_matrix_sync(cp, acc[mi][ni], DPH, wmma::mem_row_major);
            }
        }
    }
}

// ---------------------------------------------------------------------------
// LSH bucketize
// ---------------------------------------------------------------------------
__global__ __launch_bounds__(128)
void bucketize_k(const float* __restrict__ rot)
{
    __shared__ __align__(16) float rs[DPH * 64];
    const int tid = threadIdx.x;
    for (int x = tid; x < DPH * 64; x += 128) rs[x] = rot[x];
    __syncthreads();

    const int gid = blockIdx.x * 128 + tid;
    const int bh  = gid >> 12;
    const int t   = gid & (TT - 1);

    const float* qrow = g_qk + ((size_t)bh * TT + t) * DPH;

    u64 vals2[32];
#pragma unroll
    for (int x = 0; x < 32; x++) vals2[x] = 0ull;

    for (int d = 0; d < DPH; d++) {
        u64 qb = bcast2(qrow[d]);
        const u64* rr = (const u64*)(rs + d * 64);
#pragma unroll
        for (int x = 0; x < 32; x++) fma2(vals2[x], qb, rr[x]);
    }

    float vals[64];
#pragma unroll
    for (int x = 0; x < 32; x++) {
        float2 f = unpack2(vals2[x]);
        vals[2 * x] = f.x; vals[2 * x + 1] = f.y;
    }

#pragma unroll
    for (int h = 0; h < NHASH; h++) {
        float best = -INFINITY;
        int   bi   = 0;
#pragma unroll
        for (int idx = 0; idx < 64; idx++) {
            float vv = (idx < 32) ? vals[h * 32 + idx] : -vals[h * 32 + idx - 32];
            if (vv > best) { best = vv; bi = idx; }
        }
        g_bkt[((size_t)(bh * NHASH + h)) * TT + t] = (unsigned char)bi;
    }
}

// ---------------------------------------------------------------------------
// Stable counting sort per (bh, hash)
// ---------------------------------------------------------------------------
__global__ __launch_bounds__(128)
void sort_k()
{
    const int seg = blockIdx.x;
    const int tid = threadIdx.x;
    __shared__ int hist[NBUCK * 128];
    __shared__ int btot[NBUCK];

    const unsigned char* bk = g_bkt + (size_t)seg * TT;

    for (int x = tid; x < NBUCK * 128; x += 128) hist[x] = 0;
    __syncthreads();

    const int t0 = tid * 32;
    for (int j = 0; j < 32; j++) {
        int b = bk[t0 + j];
        hist[b * 128 + tid]++;
    }
    __syncthreads();

    if (tid < NBUCK) {
        int s = 0;
        for (int j = 0; j < 128; j++) s += hist[tid * 128 + j];
        btot[tid] = s;
    }
    __syncthreads();

    if (tid == 0) {
        int run = 0;
        for (int b = 0; b < NBUCK; b++) { int c = btot[b]; btot[b] = run; run += c; }
    }
    __syncthreads();

    if (tid < NBUCK) {
        int run = btot[tid];
        for (int j = 0; j < 128; j++) {
            int c = hist[tid * 128 + j];
            hist[tid * 128 + j] = run;
            run += c;
        }
    }
    __syncthreads();

    int* dst = g_st + (size_t)(seg >> 1) * (NHASH * TT) + (size_t)(seg & 1) * TT;
    for (int j = 0; j < 32; j++) {
        int t = t0 + j;
        int b = bk[t];
        int pos = hist[b * 128 + tid]++;
        dst[pos] = t;
    }
}

// ---------------------------------------------------------------------------
// Chunked LSH attention with one-chunk look-back.
// ---------------------------------------------------------------------------
__global__ __launch_bounds__(64)
void attn_k(const unsigned char* __restrict__ pad)
{
    const int c  = blockIdx.x;
    const int bh = blockIdx.y;
    const int i  = threadIdx.x;
    const int b  = bh >> 4;

    __shared__ __align__(16) float ks[WW][68];
    __shared__ __align__(16) float vs[WW][68];
    __shared__ int   tks[WW];
    __shared__ float pen[WW];

    const int* stb = g_st + (size_t)bh * (NHASH * TT);

    const int sq = c * WW + i;
    const int tq = stb[sq];

    u64 qp[32];
    {
        const u64* qrow = (const u64*)(g_qk + ((size_t)bh * TT + tq) * DPH);
#pragma unroll
        for (int x = 0; x < 32; x++) qp[x] = qrow[x];
    }

    float m = -INFINITY, l = 0.f;
    u64 accp[32];
#pragma unroll
    for (int d = 0; d < 32; d++) accp[d] = 0ull;

    for (int stg = 0; stg < 2; stg++) {
        const int kc = (stg == 0) ? c : ((c + CCHUNK - 1) & (CCHUNK - 1));
        const int sk = kc * WW + i;
        const int tk = stb[sk];

        {
            const float4* krow = (const float4*)(g_qk + ((size_t)bh * TT + tk) * DPH);
            const float4* vrow = (const float4*)(g_v  + ((size_t)bh * TT + tk) * DPH);
            float4 kr[16];
            float ss = 0.f;
#pragma unroll
            for (int x = 0; x < 16; x++) {
                kr[x] = krow[x];
                ss += kr[x].x * kr[x].x + kr[x].y * kr[x].y
                    + kr[x].z * kr[x].z + kr[x].w * kr[x].w;
            }
            float inv = 1.f / fmaxf(sqrtf(ss), 1e-6f);
#pragma unroll
            for (int x = 0; x < 16; x++) {
                *(float4*)&ks[i][4 * x] = make_float4(kr[x].x * inv, kr[x].y * inv,
                                                      kr[x].z * inv, kr[x].w * inv);
                *(float4*)&vs[i][4 * x] = vrow[x];
            }
            tks[i] = tk;
            pen[i] = pad[(size_t)b * TT + tk] ? -1e9f : 0.f;
        }
        __syncthreads();

        for (int j = 0; j < WW; j++) {
            const u64* kj = (const u64*)&ks[j][0];
            u64 s2 = 0ull;
#pragma unroll
            for (int x = 0; x < 32; x++) fma2(s2, qp[x], kj[x]);
            float2 sp = unpack2(s2);
            float s = (sp.x + sp.y) * 0.125f + pen[j];
            if (tq == tks[j]) s -= 1e5f;

            const u64* vj = (const u64*)&vs[j][0];
            if (s <= m) {
                float p = __expf(s - m);
                l += p;
                u64 pb = bcast2(p);
#pragma unroll
                for (int d = 0; d < 32; d++) fma2(accp[d], pb, vj[d]);
            } else {
                float sc = __expf(m - s);
                l = l * sc + 1.f;
                u64 scb = bcast2(sc);
#pragma unroll
                for (int d = 0; d < 32; d++) accp[d] = fma2o(accp[d], scb, vj[d]);
                m = s;
            }
        }
        __syncthreads();
    }

    const float lse  = m + __logf(l);
    const float invl = 1.f / l;
    const int   h    = sq >> 12;

    float* orow = g_o + (((size_t)(bh * NHASH + h)) * TT + tq) * DPH;
#pragma unroll
    for (int d = 0; d < 32; d++) {
        float2 f = unpack2(accp[d]);
        orow[2 * d]     = f.x * invl;
        orow[2 * d + 1] = f.y * invl;
    }
    g_lse[((size_t)(bh * NHASH + h)) * TT + tq] = lse;
}

// ---------------------------------------------------------------------------
// Combine hash rounds; fused bf16 split epilogue -> A planes for out-proj.
// ---------------------------------------------------------------------------
__global__ __launch_bounds__(256)
void combine_k()
{
    const size_t idx = (size_t)blockIdx.x * 256 + threadIdx.x;
    const int d2  = (int)(idx & 31);
    const size_t row = idx >> 5;
    const int bh  = (int)(row >> 12);
    const int t   = (int)(row & (TT - 1));

    const float l0 = g_lse[((size_t)(bh * 2 + 0)) * TT + t];
    const float l1 = g_lse[((size_t)(bh * 2 + 1)) * TT + t];
    const float mm = fmaxf(l0, l1);
    const float e0 = __expf(l0 - mm), e1 = __expf(l1 - mm);
    const float inv = 1.f / (e0 + e1);

    const float2 v0 = ((const float2*)g_o)[(((size_t)(bh * 2 + 0)) * TT + t) * 32 + d2];
    const float2 v1 = ((const float2*)g_o)[(((size_t)(bh * 2 + 1)) * TT + t) * 32 + d2];

    const float r0 = (e0 * v0.x + e1 * v1.x) * inv;
    const float r1 = (e0 * v0.y + e1 * v1.y) * inv;

    __nv_bfloat16 h0 = __float2bfloat16_rn(r0);
    __nv_bfloat16 h1 = __float2bfloat16_rn(r1);
    __nv_bfloat16 q0 = __float2bfloat16_rn(r0 - __bfloat162float(h0));
    __nv_bfloat16 q1 = __float2bfloat16_rn(r1 - __bfloat162float(h1));

    const int b = bh >> 4, n = bh & 15;
    const size_t o = (((size_t)(b * TT + t)) * NHEADS + n) * 32 + d2;
    ((unsigned*)g_ab0)[o] = (unsigned)__bfloat16_as_ushort(h0)
                          | ((unsigned)__bfloat16_as_ushort(h1) << 16);
    ((unsigned*)g_ab1)[o] = (unsigned)__bfloat16_as_ushort(q0)
                          | ((unsigned)__bfloat16_as_ushort(q1) << 16);
}

// ---------------------------------------------------------------------------
// Host entry
// ---------------------------------------------------------------------------
extern "C" void kernel_launch(void* const* d_in, const int* in_sizes, int n_in,
                              void* d_out, int out_size)
{
    const float*         x    = (const float*)d_in[0];
    const unsigned char* pad  = (const unsigned char*)d_in[1];
    const float*         wqk  = (const float*)d_in[2];
    const float*         wv   = (const float*)d_in[3];
    const float*         wo   = (const float*)d_in[4];
    const float*         rot  = (const float*)d_in[5];
    float*               out  = (float*)d_out;

    void *p_qk, *p_v, *p_ab0, *p_ab1, *p_wb0, *p_wb1;
    cudaGetSymbolAddress(&p_qk,  g_qk);
    cudaGetSymbolAddress(&p_v,   g_v);
    cudaGetSymbolAddress(&p_ab0, g_ab0);
    cudaGetSymbolAddress(&p_ab1, g_ab1);
    cudaGetSymbolAddress(&p_wb0, g_wb0);
    cudaGetSymbolAddress(&p_wb1, g_wb1);

    const int nx4 = MTOT * HID / 4;
    const int nw4 = HID * HID / 4;

    dim3 gg(HID / 128, MTOT / 128);

    // 1) qk projection: exact fp32 scalar (feeds LSH argmax)
    sgemm_qk_k<<<gg, 256>>>(x, wqk, (float*)p_qk, MTOT, HID, HID);

    // 2) v projection: hoisted bf16 split + pipelined tensor GEMM
    cvt2_k<<<(nx4 + 255) / 256, 256>>>(x, (__nv_bfloat16*)p_ab0, (__nv_bfloat16*)p_ab1, nx4);
    cvt2_k<<<(nw4 + 255) / 256, 256>>>(wv, (__nv_bfloat16*)p_wb0, (__nv_bfloat16*)p_wb1, nw4);
    tgemm_k<<<gg, 256>>>((__nv_bfloat16*)p_ab0, (__nv_bfloat16*)p_ab1,
                         (__nv_bfloat16*)p_wb0, (__nv_bfloat16*)p_wb1,
                         (float*)p_v, MTOT, HID, HID, 1);

    // 3) LSH bucketing + stable sort
    bucketize_k<<<(BH * TT) / 128, 128>>>(rot);
    sort_k<<<BH * NHASH, 128>>>();

    // 4) chunked attention
    dim3 ga(CCHUNK, BH);
    attn_k<<<ga, 64>>>(pad);

    // 5) combine -> bf16 A-planes directly (fused split epilogue)
    combine_k<<<((size_t)BH * TT * DPH / 2) / 256, 256>>>();

    // 6) output projection: pipelined tensor GEMM on fused planes
    cvt2_k<<<(nw4 + 255) / 256, 256>>>(wo, (__nv_bfloat16*)p_wb0, (__nv_bfloat16*)p_wb1, nw4);
    tgemm_k<<<gg, 256>>>((__nv_bfloat16*)p_ab0, (__nv_bfloat16*)p_ab1,
                         (__nv_bfloat16*)p_wb0, (__nv_bfloat16*)p_wb1,
                         out, MTOT, HID, HID, 0);
}

// round 16
// speedup vs baseline: 1.2142x; 1.1232x over previous
#include <cuda_runtime.h>
#include <cuda_bf16.h>
#include <mma.h>
#include <math.h>

using namespace nvcuda;

// ---------------------------------------------------------------------------
// Problem constants
// ---------------------------------------------------------------------------
#define TT      4096
#define NHEADS  16
#define BB      4
#define BH      64
#define DPH     64
#define HID     1024
#define NHASH   2
#define NBUCK   64
#define WW      64
#define CCHUNK  128
#define MTOT    16384
#define TAU     0.03f   // rotation top-2 gap threshold for exact repair

typedef unsigned long long u64;

// ---- packed fp32x2 helpers ------------------------------------------------
__device__ __forceinline__ void fma2(u64& d, u64 a, u64 b) {
    asm("fma.rn.f32x2 %0, %1, %2, %0;" : "+l"(d) : "l"(a), "l"(b));
}
__device__ __forceinline__ u64 fma2o(u64 a, u64 b, u64 c) {
    u64 d; asm("fma.rn.f32x2 %0, %1, %2, %3;" : "=l"(d) : "l"(a), "l"(b), "l"(c));
    return d;
}
__device__ __forceinline__ u64 bcast2(float f) {
    u64 r; unsigned int u = __float_as_uint(f);
    asm("mov.b64 %0, {%1, %1};" : "=l"(r) : "r"(u));
    return r;
}
__device__ __forceinline__ float2 unpack2(u64 v) {
    unsigned int lo, hi;
    asm("mov.b64 {%0, %1}, %2;" : "=r"(lo), "=r"(hi) : "l"(v));
    return make_float2(__uint_as_float(lo), __uint_as_float(hi));
}

// ---- cp.async helpers -----------------------------------------------------
__device__ __forceinline__ void cp16(void* smem, const void* gmem) {
    unsigned saddr = (unsigned)__cvta_generic_to_shared(smem);
    asm volatile("cp.async.cg.shared.global [%0], [%1], 16;"
                 :: "r"(saddr), "l"(gmem));
}
__device__ __forceinline__ void cp_commit() {
    asm volatile("cp.async.commit_group;");
}
template <int N>
__device__ __forceinline__ void cp_wait() {
    asm volatile("cp.async.wait_group %0;" :: "n"(N));
}

// ---------------------------------------------------------------------------
// Device scratch (static).
// ---------------------------------------------------------------------------
__device__ float          g_qk  [(size_t)BH * TT * DPH];
__device__ float          g_v   [(size_t)BH * TT * DPH];
__device__ float          g_o   [(size_t)BH * NHASH * TT * DPH];
__device__ float          g_lse [(size_t)BH * NHASH * TT];
__device__ int            g_st  [(size_t)BH * NHASH * TT];
__device__ unsigned char  g_bkt [(size_t)BH * NHASH * TT];
__device__ __nv_bfloat16  g_ab0 [(size_t)MTOT * HID];
__device__ __nv_bfloat16  g_ab1 [(size_t)MTOT * HID];
__device__ __nv_bfloat16  g_wb0 [(size_t)HID * HID];
__device__ __nv_bfloat16  g_wb1 [(size_t)HID * HID];
__device__ int            g_nflag;
__device__ int            g_flagged[(size_t)BH * TT];

// ---------------------------------------------------------------------------
// fp32 -> 2 bf16 planes (hi + residual).
// ---------------------------------------------------------------------------
__global__ __launch_bounds__(256)
void cvt2_k(const float* __restrict__ src, __nv_bfloat16* __restrict__ p0,
            __nv_bfloat16* __restrict__ p1, int n4)
{
    int i = blockIdx.x * 256 + threadIdx.x;
    if (i >= n4) return;
    float4 v = ((const float4*)src)[i];
    float va[4] = {v.x, v.y, v.z, v.w};
    __nv_bfloat16 t0[4], t1[4];
#pragma unroll
    for (int j = 0; j < 4; j++) {
        t0[j] = __float2bfloat16_rn(va[j]);
        t1[j] = __float2bfloat16_rn(va[j] - __bfloat162float(t0[j]));
    }
    ((uint2*)p0)[i] = *(uint2*)t0;
    ((uint2*)p1)[i] = *(uint2*)t1;
}

__global__ void zero_k() { if (threadIdx.x == 0) g_nflag = 0; }

// ===========================================================================
// bf16 tensor GEMM, pre-split planes, 2-stage cp.async pipeline.
// D = A0B0 + A0B1 + A1B0.  (proven 8.8e-6-class accuracy)
// ===========================================================================
#define KSTEP 16
#define LDA   24
#define LDB   136

static_assert((2 * 2 * 128 * LDA + 2 * 2 * KSTEP * LDB) * 2 <= 48 * 1024, "smem");

__global__ __launch_bounds__(256)
void tgemm_k(const __nv_bfloat16* __restrict__ A0, const __nv_bfloat16* __restrict__ A1,
             const __nv_bfloat16* __restrict__ B0, const __nv_bfloat16* __restrict__ B1,
             float* __restrict__ C, int M, int N, int K, int mode)
{
    __shared__ __align__(32) __nv_bfloat16 As[2][2][128][LDA];   // [stage][plane]
    __shared__ __align__(32) __nv_bfloat16 Bs[2][2][KSTEP][LDB];

    const int tid  = threadIdx.x;
    const int wid  = tid >> 5;
    const int brow = blockIdx.y * 128;
    const int bcol = blockIdx.x * 128;
    const int wm   = (wid >> 2) * 64;
    const int wn   = (wid & 3) * 32;

    const int a_row = tid >> 1, a_col = (tid & 1) * 8;
    const int b_row = tid >> 4, b_col = (tid & 15) * 8;

    const __nv_bfloat16* a0g = A0 + (size_t)(brow + a_row) * K + a_col;
    const __nv_bfloat16* a1g = A1 + (size_t)(brow + a_row) * K + a_col;
    const __nv_bfloat16* b0g = B0 + (size_t)b_row * N + bcol + b_col;
    const __nv_bfloat16* b1g = B1 + (size_t)b_row * N + bcol + b_col;

    wmma::fragment<wmma::accumulator, 16, 16, 16, float> acc[4][2];
#pragma unroll
    for (int mi = 0; mi < 4; mi++)
#pragma unroll
        for (int ni = 0; ni < 2; ni++) wmma::fill_fragment(acc[mi][ni], 0.f);

    const int nIter = K / KSTEP;

    cp16(&As[0][0][a_row][a_col], a0g);
    cp16(&As[0][1][a_row][a_col], a1g);
    cp16(&Bs[0][0][b_row][b_col], b0g);
    cp16(&Bs[0][1][b_row][b_col], b1g);
    cp_commit();

    for (int i = 0; i < nIter; i++) {
        const int stg = i & 1;

        if (i + 1 < nIter) {
            const int nk = (i + 1) * KSTEP;
            const int ns = stg ^ 1;
            cp16(&As[ns][0][a_row][a_col], a0g + nk);
            cp16(&As[ns][1][a_row][a_col], a1g + nk);
            cp16(&Bs[ns][0][b_row][b_col], b0g + (size_t)nk * N);
            cp16(&Bs[ns][1][b_row][b_col], b1g + (size_t)nk * N);
            cp_commit();
            cp_wait<1>();
        } else {
            cp_wait<0>();
        }
        __syncthreads();

        wmma::fragment<wmma::matrix_b, 16, 16, 16, __nv_bfloat16, wmma::row_major> bf[2][2];
#pragma unroll
        for (int ni = 0; ni < 2; ni++) {
            wmma::load_matrix_sync(bf[ni][0], &Bs[stg][0][0][wn + ni * 16], LDB);
            wmma::load_matrix_sync(bf[ni][1], &Bs[stg][1][0][wn + ni * 16], LDB);
        }
#pragma unroll
        for (int mi = 0; mi < 4; mi++) {
            wmma::fragment<wmma::matrix_a, 16, 16, 16, __nv_bfloat16, wmma::row_major> af0, af1;
            wmma::load_matrix_sync(af0, &As[stg][0][wm + mi * 16][0], LDA);
            wmma::load_matrix_sync(af1, &As[stg][1][wm + mi * 16][0], LDA);
#pragma unroll
            for (int ni = 0; ni < 2; ni++) {
                wmma::mma_sync(acc[mi][ni], af0, bf[ni][0], acc[mi][ni]);
                wmma::mma_sync(acc[mi][ni], af0, bf[ni][1], acc[mi][ni]);
                wmma::mma_sync(acc[mi][ni], af1, bf[ni][0], acc[mi][ni]);
            }
        }
        __syncthreads();
    }

#pragma unroll
    for (int mi = 0; mi < 4; mi++) {
#pragma unroll
        for (int ni = 0; ni < 2; ni++) {
            int m0 = brow + wm + mi * 16;
            int c0 = bcol + wn + ni * 16;
            if (mode == 0) {
                wmma::store_matrix_sync(C + (size_t)m0 * N + c0, acc[mi][ni], N,
                                        wmma::mem_row_major);
            } else {
                int b = m0 >> 12;
                int t = m0 & (TT - 1);
                int n = c0 >> 6;
                int d = c0 & 63;
                float* cp = C + (((size_t)(b * NHEADS + n) * TT + t) * DPH + d);
                wmma::store_matrix_sync(cp, acc[mi][ni], DPH, wmma::mem_row_major);
            }
        }
    }
}

// ---------------------------------------------------------------------------
// LSH bucketize with top-2 gap flagging. Buckets from tensor-qk are written
// for all tokens; tokens whose min (over hashes) top-2 rotation gap < TAU are
// appended to a worklist and later repaired with exact fp32 qk.
// ---------------------------------------------------------------------------
__global__ __launch_bounds__(128)
void bucketize_k(const float* __restrict__ rot)
{
    __shared__ __align__(16) float rs[DPH * 64];
    const int tid = threadIdx.x;
    for (int x = tid; x < DPH * 64; x += 128) rs[x] = rot[x];
    __syncthreads();

    const int gid = blockIdx.x * 128 + tid;
    const int bh  = gid >> 12;
    const int t   = gid & (TT - 1);

    const float* qrow = g_qk + ((size_t)bh * TT + t) * DPH;

    u64 vals2[32];
#pragma unroll
    for (int x = 0; x < 32; x++) vals2[x] = 0ull;

    for (int d = 0; d < DPH; d++) {
        u64 qb = bcast2(qrow[d]);
        const u64* rr = (const u64*)(rs + d * 64);
#pragma unroll
        for (int x = 0; x < 32; x++) fma2(vals2[x], qb, rr[x]);
    }

    float vals[64];
#pragma unroll
    for (int x = 0; x < 32; x++) {
        float2 f = unpack2(vals2[x]);
        vals[2 * x] = f.x; vals[2 * x + 1] = f.y;
    }

    float mingap = INFINITY;
#pragma unroll
    for (int h = 0; h < NHASH; h++) {
        float best = -INFINITY, sec = -INFINITY;
        int   bi   = 0;
#pragma unroll
        for (int idx = 0; idx < 64; idx++) {
            float vv = (idx < 32) ? vals[h * 32 + idx] : -vals[h * 32 + idx - 32];
            if (vv > best) { sec = best; best = vv; bi = idx; }
            else if (vv > sec) sec = vv;
        }
        g_bkt[((size_t)(bh * NHASH + h)) * TT + t] = (unsigned char)bi;
        mingap = fminf(mingap, best - sec);
    }
    if (mingap < TAU) {
        int pos = atomicAdd(&g_nflag, 1);
        g_flagged[pos] = gid;
    }
}

// ---------------------------------------------------------------------------
// Exact repair: for flagged tokens recompute qk row in exact fp32 from
// x . wqk, redo rotations + first-max argmax, overwrite buckets.
// One warp per flagged token; grid-strided.
// ---------------------------------------------------------------------------
__global__ __launch_bounds__(128)
void repair_k(const float* __restrict__ x, const float* __restrict__ wqk,
              const float* __restrict__ rot)
{
    __shared__ float rs[DPH * 64];
    __shared__ float qkrow[4][DPH];
    __shared__ float rotv[4][64];

    const int tid = threadIdx.x;
    const int wid = tid >> 5;
    const int lid = tid & 31;

    for (int i = tid; i < DPH * 64; i += 128) rs[i] = rot[i];
    __syncthreads();

    const int nf = g_nflag;
    for (int e = blockIdx.x * 4 + wid; e < nf; e += gridDim.x * 4) {
        const int gid = g_flagged[e];
        const int bh = gid >> 12, t = gid & (TT - 1);
        const int b = bh >> 4, n = bh & 15;

        const float* xr = x + ((size_t)b * TT + t) * HID;
        const float* wq = wqk + n * DPH;   // wqk[h][n][d] -> wq[h*HID + d]
        const int d0 = 2 * lid, d1 = d0 + 1;

        float q0 = 0.f, q1 = 0.f;
        for (int h = 0; h < HID; h++) {
            float xv = xr[h];
            q0 += xv * wq[(size_t)h * HID + d0];
            q1 += xv * wq[(size_t)h * HID + d1];
        }
        qkrow[wid][d0] = q0;
        qkrow[wid][d1] = q1;
        __syncwarp();

        float r0 = 0.f, r1 = 0.f;
        for (int d = 0; d < DPH; d++) {
            float qd = qkrow[wid][d];
            r0 += qd * rs[d * 64 + d0];
            r1 += qd * rs[d * 64 + d1];
        }
        rotv[wid][d0] = r0;
        rotv[wid][d1] = r1;
        __syncwarp();

        if (lid == 0) {
            for (int h = 0; h < NHASH; h++) {
                float best = -INFINITY; int bi = 0;
                for (int idx = 0; idx < 64; idx++) {
                    float vv = (idx < 32) ? rotv[wid][h * 32 + idx]
                                          : -rotv[wid][h * 32 + idx - 32];
                    if (vv > best) { best = vv; bi = idx; }
                }
                g_bkt[((size_t)(bh * NHASH + h)) * TT + t] = (unsigned char)bi;
            }
        }
        __syncwarp();
    }
}

// ---------------------------------------------------------------------------
// Stable counting sort per (bh, hash)
// ---------------------------------------------------------------------------
__global__ __launch_bounds__(128)
void sort_k()
{
    const int seg = blockIdx.x;
    const int tid = threadIdx.x;
    __shared__ int hist[NBUCK * 128];
    __shared__ int btot[NBUCK];

    const unsigned char* bk = g_bkt + (size_t)seg * TT;

    for (int x = tid; x < NBUCK * 128; x += 128) hist[x] = 0;
    __syncthreads();

    const int t0 = tid * 32;
    for (int j = 0; j < 32; j++) {
        int b = bk[t0 + j];
        hist[b * 128 + tid]++;
    }
    __syncthreads();

    if (tid < NBUCK) {
        int s = 0;
        for (int j = 0; j < 128; j++) s += hist[tid * 128 + j];
        btot[tid] = s;
    }
    __syncthreads();

    if (tid == 0) {
        int run = 0;
        for (int b = 0; b < NBUCK; b++) { int c = btot[b]; btot[b] = run; run += c; }
    }
    __syncthreads();

    if (tid < NBUCK) {
        int run = btot[tid];
        for (int j = 0; j < 128; j++) {
            int c = hist[tid * 128 + j];
            hist[tid * 128 + j] = run;
            run += c;
        }
    }
    __syncthreads();

    int* dst = g_st + (size_t)(seg >> 1) * (NHASH * TT) + (size_t)(seg & 1) * TT;
    for (int j = 0; j < 32; j++) {
        int t = t0 + j;
        int b = bk[t];
        int pos = hist[b * 128 + tid]++;
        dst[pos] = t;
    }
}

// ---------------------------------------------------------------------------
// Chunked LSH attention with one-chunk look-back.
// ---------------------------------------------------------------------------
__global__ __launch_bounds__(64)
void attn_k(const unsigned char* __restrict__ pad)
{
    const int c  = blockIdx.x;
    const int bh = blockIdx.y;
    const int i  = threadIdx.x;
    const int b  = bh >> 4;

    __shared__ __align__(16) float ks[WW][68];
    __shared__ __align__(16) float vs[WW][68];
    __shared__ int   tks[WW];
    __shared__ float pen[WW];

    const int* stb = g_st + (size_t)bh * (NHASH * TT);

    const int sq = c * WW + i;
    const int tq = stb[sq];

    u64 qp[32];
    {
        const u64* qrow = (const u64*)(g_qk + ((size_t)bh * TT + tq) * DPH);
#pragma unroll
        for (int x = 0; x < 32; x++) qp[x] = qrow[x];
    }

    float m = -INFINITY, l = 0.f;
    u64 accp[32];
#pragma unroll
    for (int d = 0; d < 32; d++) accp[d] = 0ull;

    for (int stg = 0; stg < 2; stg++) {
        const int kc = (stg == 0) ? c : ((c + CCHUNK - 1) & (CCHUNK - 1));
        const int sk = kc * WW + i;
        const int tk = stb[sk];

        {
            const float4* krow = (const float4*)(g_qk + ((size_t)bh * TT + tk) * DPH);
            const float4* vrow = (const float4*)(g_v  + ((size_t)bh * TT + tk) * DPH);
            float4 kr[16];
            float ss = 0.f;
#pragma unroll
            for (int x = 0; x < 16; x++) {
                kr[x] = krow[x];
                ss += kr[x].x * kr[x].x + kr[x].y * kr[x].y
                    + kr[x].z * kr[x].z + kr[x].w * kr[x].w;
            }
            float inv = 1.f / fmaxf(sqrtf(ss), 1e-6f);
#pragma unroll
            for (int x = 0; x < 16; x++) {
                *(float4*)&ks[i][4 * x] = make_float4(kr[x].x * inv, kr[x].y * inv,
                                                      kr[x].z * inv, kr[x].w * inv);
                *(float4*)&vs[i][4 * x] = vrow[x];
            }
            tks[i] = tk;
            pen[i] = pad[(size_t)b * TT + tk] ? -1e9f : 0.f;
        }
        __syncthreads();

        for (int j = 0; j < WW; j++) {
            const u64* kj = (const u64*)&ks[j][0];
            u64 s2 = 0ull;
#pragma unroll
            for (int x = 0; x < 32; x++) fma2(s2, qp[x], kj[x]);
            float2 sp = unpack2(s2);
            float s = (sp.x + sp.y) * 0.125f + pen[j];
            if (tq == tks[j]) s -= 1e5f;

            const u64* vj = (const u64*)&vs[j][0];
            if (s <= m) {
                float p = __expf(s - m);
                l += p;
                u64 pb = bcast2(p);
#pragma unroll
                for (int d = 0; d < 32; d++) fma2(accp[d], pb, vj[d]);
            } else {
                float sc = __expf(m - s);
                l = l * sc + 1.f;
                u64 scb = bcast2(sc);
#pragma unroll
                for (int d = 0; d < 32; d++) accp[d] = fma2o(accp[d], scb, vj[d]);
                m = s;
            }
        }
        __syncthreads();
    }

    const float lse  = m + __logf(l);
    const float invl = 1.f / l;
    const int   h    = sq >> 12;

    float* orow = g_o + (((size_t)(bh * NHASH + h)) * TT + tq) * DPH;
#pragma unroll
    for (int d = 0; d < 32; d++) {
        float2 f = unpack2(accp[d]);
        orow[2 * d]     = f.x * invl;
        orow[2 * d + 1] = f.y * invl;
    }
    g_lse[((size_t)(bh * NHASH + h)) * TT + tq] = lse;
}

// ---------------------------------------------------------------------------
// Combine hash rounds; fused bf16 split epilogue -> A planes for out-proj.
// ---------------------------------------------------------------------------
__global__ __launch_bounds__(256)
void combine_k()
{
    const size_t idx = (size_t)blockIdx.x * 256 + threadIdx.x;
    const int d2  = (int)(idx & 31);
    const size_t row = idx >> 5;
    const int bh  = (int)(row >> 12);
    const int t   = (int)(row & (TT - 1));

    const float l0 = g_lse[((size_t)(bh * 2 + 0)) * TT + t];
    const float l1 = g_lse[((size_t)(bh * 2 + 1)) * TT + t];
    const float mm = fmaxf(l0, l1);
    const float e0 = __expf(l0 - mm), e1 = __expf(l1 - mm);
    const float inv = 1.f / (e0 + e1);

    const float2 v0 = ((const float2*)g_o)[(((size_t)(bh * 2 + 0)) * TT + t) * 32 + d2];
    const float2 v1 = ((const float2*)g_o)[(((size_t)(bh * 2 + 1)) * TT + t) * 32 + d2];

    const float r0 = (e0 * v0.x + e1 * v1.x) * inv;
    const float r1 = (e0 * v0.y + e1 * v1.y) * inv;

    __nv_bfloat16 h0 = __float2bfloat16_rn(r0);
    __nv_bfloat16 h1 = __float2bfloat16_rn(r1);
    __nv_bfloat16 q0 = __float2bfloat16_rn(r0 - __bfloat162float(h0));
    __nv_bfloat16 q1 = __float2bfloat16_rn(r1 - __bfloat162float(h1));

    const int b = bh >> 4, n = bh & 15;
    const size_t o = (((size_t)(b * TT + t)) * NHEADS + n) * 32 + d2;
    ((unsigned*)g_ab0)[o] = (unsigned)__bfloat16_as_ushort(h0)
                          | ((unsigned)__bfloat16_as_ushort(h1) << 16);
    ((unsigned*)g_ab1)[o] = (unsigned)__bfloat16_as_ushort(q0)
                          | ((unsigned)__bfloat16_as_ushort(q1) << 16);
}

// ---------------------------------------------------------------------------
// Host entry
// ---------------------------------------------------------------------------
extern "C" void kernel_launch(void* const* d_in, const int* in_sizes, int n_in,
                              void* d_out, int out_size)
{
    const float*         x    = (const float*)d_in[0];
    const unsigned char* pad  = (const unsigned char*)d_in[1];
    const float*         wqk  = (const float*)d_in[2];
    const float*         wv   = (const float*)d_in[3];
    const float*         wo   = (const float*)d_in[4];
    const float*         rot  = (const float*)d_in[5];
    float*               out  = (float*)d_out;

    void *p_qk, *p_v, *p_ab0, *p_ab1, *p_wb0, *p_wb1;
    cudaGetSymbolAddress(&p_qk,  g_qk);
    cudaGetSymbolAddress(&p_v,   g_v);
    cudaGetSymbolAddress(&p_ab0, g_ab0);
    cudaGetSymbolAddress(&p_ab1, g_ab1);
    cudaGetSymbolAddress(&p_wb0, g_wb0);
    cudaGetSymbolAddress(&p_wb1, g_wb1);

    const int nx4 = MTOT * HID / 4;
    const int nw4 = HID * HID / 4;

    dim3 gg(HID / 128, MTOT / 128);

    // 1) split x once; qk projection on tensor path (buckets repaired below)
    cvt2_k<<<(nx4 + 255) / 256, 256>>>(x, (__nv_bfloat16*)p_ab0, (__nv_bfloat16*)p_ab1, nx4);
    cvt2_k<<<(nw4 + 255) / 256, 256>>>(wqk, (__nv_bfloat16*)p_wb0, (__nv_bfloat16*)p_wb1, nw4);
    tgemm_k<<<gg, 256>>>((__nv_bfloat16*)p_ab0, (__nv_bfloat16*)p_ab1,
                         (__nv_bfloat16*)p_wb0, (__nv_bfloat16*)p_wb1,
                         (float*)p_qk, MTOT, HID, HID, 1);

    // 2) v projection (reuses x planes; weight planes overwritten after qk)
    cvt2_k<<<(nw4 + 255) / 256, 256>>>(wv, (__nv_bfloat16*)p_wb0, (__nv_bfloat16*)p_wb1, nw4);
    tgemm_k<<<gg, 256>>>((__nv_bfloat16*)p_ab0, (__nv_bfloat16*)p_ab1,
                         (__nv_bfloat16*)p_wb0, (__nv_bfloat16*)p_wb1,
                         (float*)p_v, MTOT, HID, HID, 1);

    // 3) bucketize with gap flagging, exact repair of flagged, stable sort
    zero_k<<<1, 32>>>();
    bucketize_k<<<(BH * TT) / 128, 128>>>(rot);
    repair_k<<<512, 128>>>(x, wqk, rot);
    sort_k<<<BH * NHASH, 128>>>();

    // 4) chunked attention
    dim3 ga(CCHUNK, BH);
    attn_k<<<ga, 64>>>(pad);

    // 5) combine -> bf16 A-planes directly (fused split epilogue)
    combine_k<<<((size_t)BH * TT * DPH / 2) / 256, 256>>>();

    // 6) output projection
    cvt2_k<<<(nw4 + 255) / 256, 256>>>(wo, (__nv_bfloat16*)p_wb0, (__nv_bfloat16*)p_wb1, nw4);
    tgemm_k<<<gg, 256>>>((__nv_bfloat16*)p_ab0, (__nv_bfloat16*)p_ab1,
                         (__nv_bfloat16*)p_wb0, (__nv_bfloat16*)p_wb1,
                         out, MTOT, HID, HID, 0);
}